// round 3
// baseline (speedup 1.0000x reference)
#include <cuda_runtime.h>
#include <cstdint>

#define NN 100000
#define NE 1600000
#define HC 128            // heads*channels
#define NEG_SLOPE 0.2f
#define BN_EPS 1e-5f

// ---------------- scratch (static __device__, no allocation) ----------------
__device__ __align__(16) float g_h[(size_t)NN * HC];     // GEMM output [N,4,32]
__device__ __align__(16) float g_acc[(size_t)NN * HC];   // attention accumulator
__device__ __align__(16) float g_y[(size_t)NN * 32];     // per-layer node features
__device__ __align__(16) float g_alS[(size_t)NN * 4];
__device__ __align__(16) float g_alD[(size_t)NN * 4];
__device__ __align__(16) int   g_emax[(size_t)NN * 4];   // float bits, dual-encoded max
__device__ __align__(16) float g_den[(size_t)NN * 4];
__device__ __align__(16) float g_esc[(size_t)NE * 4];    // e then ee scratch
__device__ float g_bn[2 * 32 * 32];                      // strided sums / sumsq
__device__ float g_scale[32];
__device__ float g_shift[32];

// ---------------- helpers ----------------
__device__ __forceinline__ void atomicMaxF(int* addr, float v) {
    if (v >= 0.f) atomicMax(addr, __float_as_int(v));
    else          atomicMin((unsigned int*)addr, __float_as_uint(v));
}

__device__ __forceinline__ void red_add_v4(float4* addr, float4 v) {
    asm volatile("red.global.add.v4.f32 [%0], {%1, %2, %3, %4};"
                 :: "l"(addr), "f"(v.x), "f"(v.y), "f"(v.z), "f"(v.w) : "memory");
}

__device__ __forceinline__ float leaky(float e) {
    return e >= 0.f ? e : NEG_SLOPE * e;
}

// ---------------- GEMM + attention logits (fused prev-layer BN+ReLU) ----------------
// block = 128 threads (one per output feature f = head*32 + c), 64 nodes/block
template<int F>
__global__ void gemm_al(const float* __restrict__ x,     // [N,F]
                        const float* __restrict__ W,     // [F,128]
                        const float* __restrict__ aS,    // [128]
                        const float* __restrict__ aD,    // [128]
                        const float* __restrict__ scale, // [F] or null
                        const float* __restrict__ shift, // [F] or null
                        float* __restrict__ h,           // [N,128]
                        float* __restrict__ alS,         // [N,4]
                        float* __restrict__ alD,         // [N,4]
                        int useBN)
{
    extern __shared__ float sm[];
    float* sW = sm;            // F*128
    float* sx = sm + F * 128;  // 8*F
    const int f = threadIdx.x;
    const int lane = f & 31;
    const int head = f >> 5;

    for (int i = f; i < F * 128; i += 128) sW[i] = W[i];
    const float as = aS[f];
    const float ad = aD[f];
    __syncthreads();

    const int TM = 8;
    const int nodeBase = blockIdx.x * 64;
    const float4* sx4 = reinterpret_cast<const float4*>(sx);

    for (int t = 0; t < 64 / TM; ++t) {
        int n0 = nodeBase + t * TM;
        __syncthreads();
        for (int i = f; i < TM * F; i += 128) {
            int m = i / F, k = i - m * F;
            int n = n0 + m;
            float v = 0.f;
            if (n < NN) {
                v = x[(size_t)n * F + k];
                if (useBN) v = fmaxf(fmaf(v, scale[k], shift[k]), 0.f);
            }
            sx[i] = v;
        }
        __syncthreads();

        float acc[TM];
#pragma unroll
        for (int m = 0; m < TM; ++m) acc[m] = 0.f;

        for (int k = 0; k < F; k += 4) {
            float4 xv[TM];
#pragma unroll
            for (int m = 0; m < TM; ++m) xv[m] = sx4[(m * F + k) >> 2];
#pragma unroll
            for (int kk = 0; kk < 4; ++kk) {
                float wv = sW[(k + kk) * 128 + f];
#pragma unroll
                for (int m = 0; m < TM; ++m) {
                    float xe = (kk == 0) ? xv[m].x : (kk == 1) ? xv[m].y
                             : (kk == 2) ? xv[m].z : xv[m].w;
                    acc[m] = fmaf(xe, wv, acc[m]);
                }
            }
        }

#pragma unroll
        for (int m = 0; m < TM; ++m) {
            int n = n0 + m;
            if (n < NN) h[(size_t)n * 128 + f] = acc[m];
            float vs = acc[m] * as;
            float vd = acc[m] * ad;
#pragma unroll
            for (int o = 16; o > 0; o >>= 1) {
                vs += __shfl_down_sync(0xffffffffu, vs, o);
                vd += __shfl_down_sync(0xffffffffu, vd, o);
            }
            if (lane == 0 && n < NN) {
                alS[n * 4 + head] = vs;
                alD[n * 4 + head] = vd;
            }
        }
    }
}

// ---------------- edge pass A: e-score + leaky + segment max ----------------
__global__ void edge_max_k(const int* __restrict__ src, const int* __restrict__ dst,
                           const float4* __restrict__ alS, const float4* __restrict__ alD,
                           float4* __restrict__ esc, int* __restrict__ emax)
{
    int i = blockIdx.x * blockDim.x + threadIdx.x;
    if (i >= NE) return;
    int s = src[i], d = dst[i];
    float4 a = alS[s], b = alD[d];
    float4 e;
    e.x = leaky(a.x + b.x);
    e.y = leaky(a.y + b.y);
    e.z = leaky(a.z + b.z);
    e.w = leaky(a.w + b.w);
    esc[i] = e;
    atomicMaxF(&emax[d * 4 + 0], e.x);
    atomicMaxF(&emax[d * 4 + 1], e.y);
    atomicMaxF(&emax[d * 4 + 2], e.z);
    atomicMaxF(&emax[d * 4 + 3], e.w);
}

// ---------------- edge pass B: exp + segment sum (vectorized reduction) ----------------
__global__ void edge_exp_k(const int* __restrict__ dst,
                           float4* __restrict__ esc,
                           const int4* __restrict__ emax,
                           float4* __restrict__ den)
{
    int i = blockIdx.x * blockDim.x + threadIdx.x;
    if (i >= NE) return;
    int d = dst[i];
    float4 e = esc[i];
    int4 mb = emax[d];
    float4 ee;
    ee.x = __expf(e.x - __int_as_float(mb.x));
    ee.y = __expf(e.y - __int_as_float(mb.y));
    ee.z = __expf(e.z - __int_as_float(mb.z));
    ee.w = __expf(e.w - __int_as_float(mb.w));
    esc[i] = ee;
    red_add_v4(&den[d], ee);
}

// ---------------- edge pass C: warp-per-edge weighted scatter ----------------
__global__ void edge_scatter_k(const int* __restrict__ src, const int* __restrict__ dst,
                               const float* __restrict__ esc, const float* __restrict__ den,
                               const float4* __restrict__ h, float4* __restrict__ acc)
{
    int gidx = blockIdx.x * blockDim.x + threadIdx.x;
    int e = gidx >> 5;
    if (e >= NE) return;
    int lane = gidx & 31;
    int s = src[e], d = dst[e];
    float t = 0.f;
    if (lane < 4) t = esc[(size_t)e * 4 + lane] / den[d * 4 + lane];
    float w = 0.25f * __shfl_sync(0xffffffffu, t, lane >> 3);
    float4 hv = h[(size_t)s * 32 + lane];
    float4 mv;
    mv.x = w * hv.x; mv.y = w * hv.y; mv.z = w * hv.z; mv.w = w * hv.w;
    red_add_v4(&acc[(size_t)d * 32 + lane], mv);
}

// ---------------- finalize (head-mean + bias) + BN stats ----------------
__global__ void finalize_bn(const float* __restrict__ acc, const float* __restrict__ bias,
                            float* __restrict__ y,
                            float* __restrict__ bnsum, float* __restrict__ bnsq)
{
    __shared__ float s1[1024];
    __shared__ float s2[1024];
    int tid = threadIdx.x;
    int c = tid & 31;
    int m = tid >> 5;
    int n = blockIdx.x * 32 + m;
    float val = 0.f;
    if (n < NN) {
        const float* r = acc + (size_t)n * 128;
        val = r[c] + r[32 + c] + r[64 + c] + r[96 + c] + bias[c];
        y[(size_t)n * 32 + c] = val;
    }
    s1[tid] = val;
    s2[tid] = val * val;
    __syncthreads();
    for (int st = 512; st >= 32; st >>= 1) {
        if (tid < st) { s1[tid] += s1[tid + st]; s2[tid] += s2[tid + st]; }
        __syncthreads();
    }
    if (tid < 32) {
        atomicAdd(&bnsum[tid * 32], s1[tid]);
        atomicAdd(&bnsq[tid * 32], s2[tid]);
    }
}

__global__ void bn_params_k(const float* __restrict__ bnsum, const float* __restrict__ bnsq,
                            const float* __restrict__ g, const float* __restrict__ be,
                            float* __restrict__ scale, float* __restrict__ shift)
{
    int c = threadIdx.x;
    if (c >= 32) return;
    float mu = bnsum[c * 32] * (1.f / NN);
    float var = bnsq[c * 32] * (1.f / NN) - mu * mu;
    float sc = g[c] * rsqrtf(var + BN_EPS);
    scale[c] = sc;
    shift[c] = be[c] - mu * sc;
}

__global__ void finalize_last(const float* __restrict__ acc, const float* __restrict__ bias,
                              float* __restrict__ out)
{
    int idx = blockIdx.x * blockDim.x + threadIdx.x;
    if (idx >= NN * 32) return;
    int n = idx >> 5;
    int c = idx & 31;
    const float* r = acc + (size_t)n * 128;
    out[idx] = r[c] + r[32 + c] + r[64 + c] + r[96 + c] + bias[c];
}

// ---------------- host ----------------
extern "C" void kernel_launch(void* const* d_in, const int* in_sizes, int n_in,
                              void* d_out, int out_size)
{
    const float* x   = (const float*)d_in[0];
    const int*   ei  = (const int*)  d_in[1];
    const float* ea  = (const float*)d_in[2];
    const float* W[3]   = {(const float*)d_in[3],  (const float*)d_in[9],  (const float*)d_in[15]};
    const float* aS[3]  = {(const float*)d_in[4],  (const float*)d_in[10], (const float*)d_in[16]};
    const float* aD[3]  = {(const float*)d_in[5],  (const float*)d_in[11], (const float*)d_in[17]};
    const float* bia[3] = {(const float*)d_in[6],  (const float*)d_in[12], (const float*)d_in[18]};
    const float* gam[2] = {(const float*)d_in[7],  (const float*)d_in[13]};
    const float* bet[2] = {(const float*)d_in[8],  (const float*)d_in[14]};
    const int* src = ei;
    const int* dst = ei + NE;

    void *ph, *pacc, *py, *pals, *pald, *pemax, *pden, *pesc, *pbn, *psc, *psh;
    cudaGetSymbolAddress(&ph, g_h);
    cudaGetSymbolAddress(&pacc, g_acc);
    cudaGetSymbolAddress(&py, g_y);
    cudaGetSymbolAddress(&pals, g_alS);
    cudaGetSymbolAddress(&pald, g_alD);
    cudaGetSymbolAddress(&pemax, g_emax);
    cudaGetSymbolAddress(&pden, g_den);
    cudaGetSymbolAddress(&pesc, g_esc);
    cudaGetSymbolAddress(&pbn, g_bn);
    cudaGetSymbolAddress(&psc, g_scale);
    cudaGetSymbolAddress(&psh, g_shift);

    cudaFuncSetAttribute(gemm_al<128>, cudaFuncAttributeMaxDynamicSharedMemorySize, 70000);

    const int GEMM_BLOCKS = (NN + 63) / 64;       // 1563
    const int EB = (NE + 255) / 256;              // 6250
    const int SCB = (NE * 32) / 256;              // 200000
    const int FB = NN / 32;                       // 3125
    const int LB = (NN * 32) / 256;               // 12500

    for (int L = 0; L < 3; ++L) {
        cudaMemsetAsync(pacc, 0, (size_t)NN * 128 * sizeof(float));
        cudaMemsetAsync(pden, 0, (size_t)NN * 4 * sizeof(float));
        cudaMemsetAsync(pemax, 0xFF, (size_t)NN * 4 * sizeof(int));
        cudaMemsetAsync(pbn, 0, 2 * 32 * 32 * sizeof(float));

        if (L == 0) {
            gemm_al<128><<<GEMM_BLOCKS, 128, 128 * 128 * 4 + 8 * 128 * 4>>>(
                x, W[0], aS[0], aD[0], nullptr, nullptr,
                (float*)ph, (float*)pals, (float*)pald, 0);
        } else {
            gemm_al<32><<<GEMM_BLOCKS, 128, 32 * 128 * 4 + 8 * 32 * 4>>>(
                (const float*)py, W[L], aS[L], aD[L],
                (const float*)psc, (const float*)psh,
                (float*)ph, (float*)pals, (float*)pald, 1);
        }

        edge_max_k<<<EB, 256>>>(src, dst, (const float4*)pals, (const float4*)pald,
                                (float4*)pesc, (int*)pemax);
        edge_exp_k<<<EB, 256>>>(dst, (float4*)pesc, (const int4*)pemax, (float4*)pden);
        edge_scatter_k<<<SCB, 256>>>(src, dst, (const float*)pesc, (const float*)pden,
                                     (const float4*)ph, (float4*)pacc);

        if (L < 2) {
            finalize_bn<<<FB, 1024>>>((const float*)pacc, bia[L], (float*)py,
                                      (float*)pbn, (float*)pbn + 1024);
            bn_params_k<<<1, 32>>>((const float*)pbn, (const float*)pbn + 1024,
                                   gam[L], bet[L], (float*)psc, (float*)psh);
        } else {
            finalize_last<<<LB, 256>>>((const float*)pacc, bia[2], (float*)d_out);
        }
    }

    cudaMemcpyAsync((float*)d_out + (size_t)NN * 32, ea,
                    (size_t)NE * 8 * sizeof(float), cudaMemcpyDeviceToDevice);
}

// round 4
// speedup vs baseline: 2.3396x; 2.3396x over previous
#include <cuda_runtime.h>
#include <cstdint>

#define NN 100000
#define NE 1600000
#define NEG_SLOPE 0.2f
#define BN_EPS 1e-5f

// ---------------- scratch (static __device__, no allocation) ----------------
__device__ __align__(16) float g_h[(size_t)NN * 128];   // GEMM output [N,4,32]
__device__ __align__(16) float g_y[(size_t)NN * 32];    // per-layer node features
__device__ __align__(16) float g_alS[(size_t)NN * 4];
__device__ __align__(16) float g_alD[(size_t)NN * 4];
__device__ int g_deg[NN];
__device__ int g_rowptr[NN + 1];
__device__ int g_cursor[NN];
__device__ int g_csr_src[NE];
__device__ float g_bn[2 * 32 * 32];                     // strided sums / sumsq
__device__ float g_scale[32];
__device__ float g_shift[32];

__device__ __forceinline__ float leaky(float e) {
    return e >= 0.f ? e : NEG_SLOPE * e;
}

// ---------------- CSR build ----------------
__global__ void hist_k(const int* __restrict__ dst, int* __restrict__ deg) {
    int i = blockIdx.x * blockDim.x + threadIdx.x;
    if (i < NE) atomicAdd(&deg[dst[i]], 1);
}

// single block, 1024 threads: chunked exclusive scan of deg -> rowptr, cursor
__global__ void scan_k(const int* __restrict__ deg, int* __restrict__ rowptr,
                       int* __restrict__ cursor) {
    __shared__ int sc[1024];
    const int tid = threadIdx.x;
    const int CH = (NN + 1023) / 1024;  // 98
    const int base = tid * CH;
    int s = 0;
    for (int i = 0; i < CH; ++i) {
        int idx = base + i;
        if (idx < NN) s += deg[idx];
    }
    sc[tid] = s;
    __syncthreads();
    // Hillis-Steele inclusive scan
    for (int off = 1; off < 1024; off <<= 1) {
        int v = (tid >= off) ? sc[tid - off] : 0;
        __syncthreads();
        sc[tid] += v;
        __syncthreads();
    }
    int run = sc[tid] - s;  // exclusive prefix for this chunk
    for (int i = 0; i < CH; ++i) {
        int idx = base + i;
        if (idx < NN) {
            rowptr[idx] = run;
            cursor[idx] = run;
            run += deg[idx];
        }
    }
    if (tid == 1023) rowptr[NN] = sc[1023];
}

__global__ void scatter_build_k(const int* __restrict__ src, const int* __restrict__ dst,
                                int* __restrict__ cursor, int* __restrict__ csr_src) {
    int i = blockIdx.x * blockDim.x + threadIdx.x;
    if (i >= NE) return;
    int p = atomicAdd(&cursor[dst[i]], 1);
    csr_src[p] = src[i];
}

// ---------------- GEMM + attention logits (fused prev-layer BN+ReLU) ----------------
template<int F>
__global__ void gemm_al(const float* __restrict__ x,     // [N,F]
                        const float* __restrict__ W,     // [F,128]
                        const float* __restrict__ aS,    // [128]
                        const float* __restrict__ aD,    // [128]
                        const float* __restrict__ scale, // [F] or null
                        const float* __restrict__ shift, // [F] or null
                        float* __restrict__ h,           // [N,128]
                        float* __restrict__ alS,         // [N,4]
                        float* __restrict__ alD,         // [N,4]
                        int useBN)
{
    extern __shared__ float sm[];
    float* sW = sm;            // F*128
    float* sx = sm + F * 128;  // 8*F
    const int f = threadIdx.x;
    const int lane = f & 31;
    const int head = f >> 5;

    for (int i = f; i < F * 128; i += 128) sW[i] = W[i];
    const float as = aS[f];
    const float ad = aD[f];
    __syncthreads();

    const int TM = 8;
    const int nodeBase = blockIdx.x * 64;
    const float4* sx4 = reinterpret_cast<const float4*>(sx);

    for (int t = 0; t < 64 / TM; ++t) {
        int n0 = nodeBase + t * TM;
        __syncthreads();
        for (int i = f; i < TM * F; i += 128) {
            int m = i / F, k = i - m * F;
            int n = n0 + m;
            float v = 0.f;
            if (n < NN) {
                v = x[(size_t)n * F + k];
                if (useBN) v = fmaxf(fmaf(v, scale[k], shift[k]), 0.f);
            }
            sx[i] = v;
        }
        __syncthreads();

        float acc[TM];
#pragma unroll
        for (int m = 0; m < TM; ++m) acc[m] = 0.f;

        for (int k = 0; k < F; k += 4) {
            float4 xv[TM];
#pragma unroll
            for (int m = 0; m < TM; ++m) xv[m] = sx4[(m * F + k) >> 2];
#pragma unroll
            for (int kk = 0; kk < 4; ++kk) {
                float wv = sW[(k + kk) * 128 + f];
#pragma unroll
                for (int m = 0; m < TM; ++m) {
                    float xe = (kk == 0) ? xv[m].x : (kk == 1) ? xv[m].y
                             : (kk == 2) ? xv[m].z : xv[m].w;
                    acc[m] = fmaf(xe, wv, acc[m]);
                }
            }
        }

#pragma unroll
        for (int m = 0; m < TM; ++m) {
            int n = n0 + m;
            if (n < NN) h[(size_t)n * 128 + f] = acc[m];
            float vs = acc[m] * as;
            float vd = acc[m] * ad;
#pragma unroll
            for (int o = 16; o > 0; o >>= 1) {
                vs += __shfl_down_sync(0xffffffffu, vs, o);
                vd += __shfl_down_sync(0xffffffffu, vd, o);
            }
            if (lane == 0 && n < NN) {
                alS[n * 4 + head] = vs;
                alD[n * 4 + head] = vd;
            }
        }
    }
}

// ---------------- fused attention + aggregate + head-mean + bias ----------------
// warp per dst node; lane = head*8 + pos (pos indexes 8 float4 = 32 channels)
__global__ void gather_k(const int* __restrict__ rowptr,
                         const int* __restrict__ csr_src,
                         const float* __restrict__ alS,   // [N,4]
                         const float* __restrict__ alD,   // [N,4]
                         const float4* __restrict__ h,    // [N,32] float4
                         const float4* __restrict__ bias4,// [8]
                         float4* __restrict__ out4)       // [N,8] float4
{
    int gid = blockIdx.x * blockDim.x + threadIdx.x;
    int n = gid >> 5;
    if (n >= NN) return;
    const int lane = gid & 31;
    const int head = lane >> 3;

    const int beg = rowptr[n];
    const int end = rowptr[n + 1];
    const float ad = alD[n * 4 + head];

    // pass 1: softmax denominator (per-head, replicated across 8 lanes)
    float den = 0.f;
    for (int k = beg; k < end; ++k) {
        int s = csr_src[k];
        float e = leaky(alS[s * 4 + head] + ad);
        den += __expf(e);
    }
    const float wsc = 0.25f / den;  // deg==0 -> loop below empty, wsc unused

    // pass 2: weighted aggregation with src-id prefetch
    float4 acc = make_float4(0.f, 0.f, 0.f, 0.f);
    int k = beg;
    int s = (k < end) ? csr_src[k] : 0;
    while (k < end) {
        int s_next = (k + 1 < end) ? csr_src[k + 1] : 0;
        float e = leaky(alS[s * 4 + head] + ad);
        float w = __expf(e) * wsc;
        float4 hv = h[(size_t)s * 32 + lane];
        acc.x = fmaf(w, hv.x, acc.x);
        acc.y = fmaf(w, hv.y, acc.y);
        acc.z = fmaf(w, hv.z, acc.z);
        acc.w = fmaf(w, hv.w, acc.w);
        s = s_next;
        ++k;
    }

    // head mean: sum the 4 heads (lanes differing in bits 3,4)
#pragma unroll
    for (int off = 8; off <= 16; off <<= 1) {
        acc.x += __shfl_xor_sync(0xffffffffu, acc.x, off);
        acc.y += __shfl_xor_sync(0xffffffffu, acc.y, off);
        acc.z += __shfl_xor_sync(0xffffffffu, acc.z, off);
        acc.w += __shfl_xor_sync(0xffffffffu, acc.w, off);
    }

    if (lane < 8) {
        float4 b = bias4[lane];
        float4 r;
        r.x = acc.x + b.x; r.y = acc.y + b.y;
        r.z = acc.z + b.z; r.w = acc.w + b.w;
        out4[(size_t)n * 8 + lane] = r;
    }
}

// ---------------- BN stats over y ----------------
__global__ void bn_stats_k(const float* __restrict__ y,
                           float* __restrict__ bnsum, float* __restrict__ bnsq)
{
    __shared__ float s1[1024];
    __shared__ float s2[1024];
    int tid = threadIdx.x;
    int c = tid & 31;
    int n = blockIdx.x * 32 + (tid >> 5);
    float val = (n < NN) ? y[(size_t)n * 32 + c] : 0.f;
    s1[tid] = val;
    s2[tid] = val * val;
    __syncthreads();
    for (int st = 512; st >= 32; st >>= 1) {
        if (tid < st) { s1[tid] += s1[tid + st]; s2[tid] += s2[tid + st]; }
        __syncthreads();
    }
    if (tid < 32) {
        atomicAdd(&bnsum[tid * 32], s1[tid]);
        atomicAdd(&bnsq[tid * 32], s2[tid]);
    }
}

__global__ void bn_params_k(const float* __restrict__ bnsum, const float* __restrict__ bnsq,
                            const float* __restrict__ g, const float* __restrict__ be,
                            float* __restrict__ scale, float* __restrict__ shift)
{
    int c = threadIdx.x;
    if (c >= 32) return;
    float mu = bnsum[c * 32] * (1.f / NN);
    float var = bnsq[c * 32] * (1.f / NN) - mu * mu;
    float sc = g[c] * rsqrtf(var + BN_EPS);
    scale[c] = sc;
    shift[c] = be[c] - mu * sc;
}

// ---------------- host ----------------
extern "C" void kernel_launch(void* const* d_in, const int* in_sizes, int n_in,
                              void* d_out, int out_size)
{
    const float* x   = (const float*)d_in[0];
    const int*   ei  = (const int*)  d_in[1];
    const float* ea  = (const float*)d_in[2];
    const float* W[3]   = {(const float*)d_in[3],  (const float*)d_in[9],  (const float*)d_in[15]};
    const float* aS[3]  = {(const float*)d_in[4],  (const float*)d_in[10], (const float*)d_in[16]};
    const float* aD[3]  = {(const float*)d_in[5],  (const float*)d_in[11], (const float*)d_in[17]};
    const float* bia[3] = {(const float*)d_in[6],  (const float*)d_in[12], (const float*)d_in[18]};
    const float* gam[2] = {(const float*)d_in[7],  (const float*)d_in[13]};
    const float* bet[2] = {(const float*)d_in[8],  (const float*)d_in[14]};
    const int* src = ei;
    const int* dst = ei + NE;

    void *ph, *py, *pals, *pald, *pdeg, *prow, *pcur, *pcsr, *pbn, *psc, *psh;
    cudaGetSymbolAddress(&ph, g_h);
    cudaGetSymbolAddress(&py, g_y);
    cudaGetSymbolAddress(&pals, g_alS);
    cudaGetSymbolAddress(&pald, g_alD);
    cudaGetSymbolAddress(&pdeg, g_deg);
    cudaGetSymbolAddress(&prow, g_rowptr);
    cudaGetSymbolAddress(&pcur, g_cursor);
    cudaGetSymbolAddress(&pcsr, g_csr_src);
    cudaGetSymbolAddress(&pbn, g_bn);
    cudaGetSymbolAddress(&psc, g_scale);
    cudaGetSymbolAddress(&psh, g_shift);

    cudaFuncSetAttribute(gemm_al<128>, cudaFuncAttributeMaxDynamicSharedMemorySize, 70000);

    const int GEMM_BLOCKS = (NN + 63) / 64;       // 1563
    const int EB = (NE + 255) / 256;              // 6250
    const int GB = (NN * 32 + 255) / 256;         // 12500
    const int BB = (NN + 31) / 32;                // 3125

    // ---- CSR build (once; reused by all 3 layers) ----
    cudaMemsetAsync(pdeg, 0, NN * sizeof(int));
    hist_k<<<EB, 256>>>(dst, (int*)pdeg);
    scan_k<<<1, 1024>>>((const int*)pdeg, (int*)prow, (int*)pcur);
    scatter_build_k<<<EB, 256>>>(src, dst, (int*)pcur, (int*)pcsr);

    for (int L = 0; L < 3; ++L) {
        if (L == 0) {
            gemm_al<128><<<GEMM_BLOCKS, 128, 128 * 128 * 4 + 8 * 128 * 4>>>(
                x, W[0], aS[0], aD[0], nullptr, nullptr,
                (float*)ph, (float*)pals, (float*)pald, 0);
        } else {
            gemm_al<32><<<GEMM_BLOCKS, 128, 32 * 128 * 4 + 8 * 32 * 4>>>(
                (const float*)py, W[L], aS[L], aD[L],
                (const float*)psc, (const float*)psh,
                (float*)ph, (float*)pals, (float*)pald, 1);
        }

        float* dest = (L < 2) ? (float*)py : (float*)d_out;
        gather_k<<<GB, 256>>>((const int*)prow, (const int*)pcsr,
                              (const float*)pals, (const float*)pald,
                              (const float4*)ph, (const float4*)bia[L],
                              (float4*)dest);

        if (L < 2) {
            cudaMemsetAsync(pbn, 0, 2 * 32 * 32 * sizeof(float));
            bn_stats_k<<<BB, 1024>>>((const float*)py, (float*)pbn, (float*)pbn + 1024);
            bn_params_k<<<1, 32>>>((const float*)pbn, (const float*)pbn + 1024,
                                   gam[L], bet[L], (float*)psc, (float*)psh);
        }
    }

    cudaMemcpyAsync((float*)d_out + (size_t)NN * 32, ea,
                    (size_t)NE * 8 * sizeof(float), cudaMemcpyDeviceToDevice);
}